// round 1
// baseline (speedup 1.0000x reference)
#include <cuda_runtime.h>
#include <cstdint>

#define B_   128
#define T_   1024
#define D_   256
#define HS_  512
#define G4_  2048            // 4*HS
#define M1_  (B_ * T_)       // 131072

#define NCTA 128
#define NTHR 256

// ---------------- device scratch (no runtime allocation allowed) ----------------
__device__ float g_xw[(size_t)M1_ * G4_];      // 1 GiB: x@W + bias, [b*T+t][2048]
__device__ float g_hbuf[2][HS_ * B_];          // h double buffer, [parity][k*128 + row]
__device__ unsigned int g_bar_arrive;
__device__ volatile unsigned int g_bar_epoch;

// ---------------- init: zero h0 and barrier state (deterministic each call) -----
__global__ void init_kernel() {
    int i = blockIdx.x * blockDim.x + threadIdx.x;
    if (i == 0) { g_bar_arrive = 0; g_bar_epoch = 0; }
    if (i < HS_ * B_) g_hbuf[0][i] = 0.0f;
}

// ---------------- phase 1: xW = x @ W + bias  (fp32 SIMT sgemm) -----------------
// A: [131072, 256] row-major (x), Bm: [256, 2048] row-major (W), C = g_xw
__global__ __launch_bounds__(256) void xw_gemm(const float* __restrict__ A,
                                               const float* __restrict__ Wm,
                                               const float* __restrict__ bias) {
    __shared__ float As[16][128];
    __shared__ float Bs[16][128];
    const int tid = threadIdx.x;
    const int bm = blockIdx.y, bn = blockIdx.x;
    const int rowA = bm * 128;
    const int colB = bn * 128;

    const int aRow = tid >> 2;          // 0..63
    const int aCol = (tid & 3) * 4;     // 0,4,8,12
    const int bRow = tid >> 5;          // 0..7
    const int bCol = (tid & 31) * 4;    // 0..124

    const int ty = tid >> 4, tx = tid & 15;

    float acc[8][8];
#pragma unroll
    for (int i = 0; i < 8; i++)
#pragma unroll
        for (int j = 0; j < 8; j++) acc[i][j] = 0.f;

    for (int k0 = 0; k0 < D_; k0 += 16) {
#pragma unroll
        for (int h = 0; h < 2; h++) {
            float4 v = *(const float4*)&A[(size_t)(rowA + aRow + h * 64) * D_ + k0 + aCol];
            As[aCol + 0][aRow + h * 64] = v.x;
            As[aCol + 1][aRow + h * 64] = v.y;
            As[aCol + 2][aRow + h * 64] = v.z;
            As[aCol + 3][aRow + h * 64] = v.w;
        }
#pragma unroll
        for (int h = 0; h < 2; h++) {
            float4 v = *(const float4*)&Wm[(size_t)(k0 + bRow + h * 8) * G4_ + colB + bCol];
            *(float4*)&Bs[bRow + h * 8][bCol] = v;
        }
        __syncthreads();

#pragma unroll
        for (int kk = 0; kk < 16; kk++) {
            float ra[8], rb[8];
            float4 a0 = *(const float4*)&As[kk][ty * 8];
            float4 a1 = *(const float4*)&As[kk][ty * 8 + 4];
            float4 b0 = *(const float4*)&Bs[kk][tx * 8];
            float4 b1 = *(const float4*)&Bs[kk][tx * 8 + 4];
            ra[0]=a0.x; ra[1]=a0.y; ra[2]=a0.z; ra[3]=a0.w;
            ra[4]=a1.x; ra[5]=a1.y; ra[6]=a1.z; ra[7]=a1.w;
            rb[0]=b0.x; rb[1]=b0.y; rb[2]=b0.z; rb[3]=b0.w;
            rb[4]=b1.x; rb[5]=b1.y; rb[6]=b1.z; rb[7]=b1.w;
#pragma unroll
            for (int i = 0; i < 8; i++)
#pragma unroll
                for (int j = 0; j < 8; j++)
                    acc[i][j] += ra[i] * rb[j];
        }
        __syncthreads();
    }

#pragma unroll
    for (int i = 0; i < 8; i++) {
        size_t r = (size_t)(rowA + ty * 8 + i);
#pragma unroll
        for (int j = 0; j < 8; j += 4) {
            int c = colB + tx * 8 + j;
            float4 v;
            v.x = acc[i][j + 0] + bias[c + 0];
            v.y = acc[i][j + 1] + bias[c + 1];
            v.z = acc[i][j + 2] + bias[c + 2];
            v.w = acc[i][j + 3] + bias[c + 3];
            *(float4*)&g_xw[r * G4_ + c] = v;
        }
    }
}

// ---------------- activations --------------------------------------------------
__device__ __forceinline__ float sigmoid_fast(float x) {
    return 1.f / (1.f + __expf(-x));
}
__device__ __forceinline__ float tanh_fast(float x) {
    float e = __expf(2.f * x);
    return 1.f - 2.f / (e + 1.f);
}

// ---------------- phase 2: persistent LSTM recurrence ---------------------------
// 128 CTAs, CTA owns 4 h-cols (=> 16 gate cols: [i0..3, f0..3, g0..3, o0..3]).
// U slice lives in SMEM for the whole kernel. h double-buffered in global.
__global__ __launch_bounds__(NTHR) void lstm_rec(const float* __restrict__ U,
                                                 float* __restrict__ out,
                                                 int write_hc) {
    extern __shared__ float smem[];
    float* Us     = smem;                   // 512*16  = 8192 floats
    float* h_s    = Us + HS_ * 16;          // 128*128 = 16384
    float* xw_s   = h_s + 128 * B_;         // 16*128  = 2048
    float* gate_s = xw_s + 16 * B_;         // 16*128  = 2048

    const int tid = threadIdx.x;
    const int cta = blockIdx.x;

    // load persistent U slice: Us[k*16 + c], c = gate*4 + hcol
    for (int idx = tid; idx < HS_ * 16; idx += NTHR) {
        int k = idx >> 4, c = idx & 15;
        int gc = (c >> 2) * HS_ + cta * 4 + (c & 3);
        Us[idx] = U[(size_t)k * G4_ + gc];
    }

    // MMA thread mapping: 8 warps = 2 (row) x 4 (col); lane = 16 x 2
    const int w  = tid >> 5, l = tid & 31;
    const int wr = w >> 2,  wc = w & 3;
    const int lr = l >> 1,  lc = l & 1;
    const int r0 = wr * 64 + lr * 4;   // rows r0..r0+3
    const int c0 = wc * 4 + lc * 2;    // gate cols c0..c0+1

    // elementwise mapping: 2 (row,hcol) cells per thread
    const int hc  = tid >> 6;          // 0..3
    const int re  = (tid & 63) * 2;    // even row
    const int hcg = cta * 4 + hc;      // global h column

    float creg[2] = {0.f, 0.f};
    float hout[2] = {0.f, 0.f};

    __syncthreads();   // Us ready

    float4 hreg[16];

    for (int t = 0; t < T_; t++) {
        const int p = t & 1;
        const float* hb_r = g_hbuf[p];
        float* hb_w = g_hbuf[1 - p];

        // stage xw[:, t, our 16 cols] -> xw_s[c][row]
        for (int i = tid; i < 512; i += NTHR) {
            int row = i & 127, gate = i >> 7;
            const float4 v = *(const float4*)&g_xw[((size_t)row * T_ + t) * G4_ + gate * HS_ + cta * 4];
            xw_s[(gate * 4 + 0) * B_ + row] = v.x;
            xw_s[(gate * 4 + 1) * B_ + row] = v.y;
            xw_s[(gate * 4 + 2) * B_ + row] = v.z;
            xw_s[(gate * 4 + 3) * B_ + row] = v.w;
        }

        // preload h chunk 0 into registers (overlap with xw staging latency)
#pragma unroll
        for (int i = 0; i < 16; i++)
            hreg[i] = __ldcg((const float4*)hb_r + tid + i * NTHR);

        __syncthreads();   // xw_s ready, prev-step gate_s consumed

        float acc[4][2];
#pragma unroll
        for (int i = 0; i < 4; i++)
#pragma unroll
            for (int j = 0; j < 2; j++)
                acc[i][j] = xw_s[(c0 + j) * B_ + r0 + i];

        // K = 512 in 4 chunks of 128, register-staged double buffering
        for (int kc = 0; kc < 4; kc++) {
#pragma unroll
            for (int i = 0; i < 16; i++)
                ((float4*)h_s)[tid + i * NTHR] = hreg[i];
            __syncthreads();
            if (kc < 3) {
#pragma unroll
                for (int i = 0; i < 16; i++)
                    hreg[i] = __ldcg((const float4*)hb_r + (kc + 1) * 4096 + tid + i * NTHR);
            }
            const float* usb = Us + (kc * 128) * 16;
#pragma unroll 4
            for (int kk = 0; kk < 128; kk++) {
                const float4 hv = *(const float4*)&h_s[kk * B_ + r0];
                const float2 uv = *(const float2*)&usb[kk * 16 + c0];
                acc[0][0] += hv.x * uv.x;  acc[0][1] += hv.x * uv.y;
                acc[1][0] += hv.y * uv.x;  acc[1][1] += hv.y * uv.y;
                acc[2][0] += hv.z * uv.x;  acc[2][1] += hv.z * uv.y;
                acc[3][0] += hv.w * uv.x;  acc[3][1] += hv.w * uv.y;
            }
            __syncthreads();
        }

        // exchange gates through SMEM
#pragma unroll
        for (int i = 0; i < 4; i++)
#pragma unroll
            for (int j = 0; j < 2; j++)
                gate_s[(c0 + j) * B_ + r0 + i] = acc[i][j];
        __syncthreads();

        // elementwise LSTM cell update (c persistent in registers)
        float hv2[2];
#pragma unroll
        for (int j = 0; j < 2; j++) {
            const int r = re + j;
            const float gi = gate_s[(0  + hc) * B_ + r];
            const float gf = gate_s[(4  + hc) * B_ + r];
            const float gg = gate_s[(8  + hc) * B_ + r];
            const float go = gate_s[(12 + hc) * B_ + r];
            const float iv  = sigmoid_fast(gi);
            const float fv  = sigmoid_fast(gf);
            const float gvt = tanh_fast(gg);
            const float ov  = sigmoid_fast(go);
            float c = fv * creg[j] + iv * gvt;
            creg[j] = c;
            float h = ov * tanh_fast(c);
            hv2[j] = h;
            out[(size_t)r * (T_ * HS_) + (size_t)t * HS_ + hcg] = h;
        }
        hout[0] = hv2[0];
        hout[1] = hv2[1];
        *(float2*)&hb_w[hcg * B_ + re] = make_float2(hv2[0], hv2[1]);

        // grid-wide dependency barrier (skip after last step)
        if (t < T_ - 1) {
            __syncthreads();
            if (tid == 0) {
                __threadfence();
                unsigned int old = atomicAdd(&g_bar_arrive, 1);
                if (old == NCTA - 1) {
                    atomicExch(&g_bar_arrive, 0);
                    __threadfence();
                    g_bar_epoch = (unsigned)(t + 1);
                } else {
                    while (g_bar_epoch < (unsigned)(t + 1)) { }
                    __threadfence();
                }
            }
            __syncthreads();
        }
    }

    if (write_hc) {
        const size_t OH = (size_t)B_ * T_ * HS_;
        out[OH + (size_t)re * HS_ + hcg]             = hout[0];
        out[OH + (size_t)(re + 1) * HS_ + hcg]       = hout[1];
        out[OH + (size_t)B_ * HS_ + (size_t)re * HS_ + hcg]       = creg[0];
        out[OH + (size_t)B_ * HS_ + (size_t)(re + 1) * HS_ + hcg] = creg[1];
    }
}

// ---------------- launch --------------------------------------------------------
extern "C" void kernel_launch(void* const* d_in, const int* in_sizes, int n_in,
                              void* d_out, int out_size) {
    const float* x    = (const float*)d_in[0];  // [128,1024,256]
    const float* Wm   = (const float*)d_in[1];  // [256,2048]
    const float* U    = (const float*)d_in[2];  // [512,2048]
    const float* bias = (const float*)d_in[3];  // [2048]
    float* out = (float*)d_out;

    (void)in_sizes; (void)n_in;

    const int smem_rec = (HS_ * 16 + 128 * B_ + 16 * B_ + 16 * B_) * (int)sizeof(float); // 114688 B
    cudaFuncSetAttribute(lstm_rec, cudaFuncAttributeMaxDynamicSharedMemorySize, smem_rec);

    const long long need_hc = (long long)B_ * T_ * HS_ + 2LL * B_ * HS_;
    int write_hc = ((long long)out_size >= need_hc) ? 1 : 0;

    init_kernel<<<(HS_ * B_ + 255) / 256, 256>>>();
    xw_gemm<<<dim3(G4_ / 128, M1_ / 128), 256>>>(x, Wm, bias);
    lstm_rec<<<NCTA, NTHR, smem_rec>>>(U, out, write_hc);
}

// round 4
// speedup vs baseline: 1.5684x; 1.5684x over previous
#include <cuda_runtime.h>
#include <cuda_bf16.h>
#include <cstdint>

#define B_   128
#define T_   1024
#define D_   256
#define HS_  512
#define G4_  2048
#define M1_  (B_ * T_)

#define RCTA 64
#define RTHR 256

// ---------------- device scratch ----------------
__device__ float g_xw[(size_t)M1_ * G4_];     // [(b*T+t)*2048 + pc]
__device__ uint4 g_uf[RCTA * 32 * 4 * 32];    // U frags: [cta][kt][nt][lane] = {b0h,b1h,b0l,b1l}
__device__ uint4 g_hfh[2][8 * 32 * 32];       // h hi A-frags: [par][(mt*32+kt)*32+lane] = {a0..a3}
__device__ uint4 g_hfl[2][8 * 32 * 32];       // h lo A-frags
__device__ unsigned int g_bar_arrive;
__device__ volatile unsigned int g_bar_epoch;

// ---------------- helpers ----------------
__device__ __forceinline__ uint32_t packbf(__nv_bfloat16 a, __nv_bfloat16 b) {
    return ((uint32_t)(*(uint16_t*)&b) << 16) | (uint32_t)(*(uint16_t*)&a);
}
__device__ __forceinline__ void split2(float a, float b, uint32_t& hi, uint32_t& lo) {
    __nv_bfloat16 ah = __float2bfloat16(a), bh = __float2bfloat16(b);
    __nv_bfloat16 al = __float2bfloat16(a - __bfloat162float(ah));
    __nv_bfloat16 bl = __float2bfloat16(b - __bfloat162float(bh));
    hi = packbf(ah, bh);
    lo = packbf(al, bl);
}
__device__ __forceinline__ void mma16816(float* d, const uint4& a, uint32_t b0, uint32_t b1) {
    asm volatile(
        "mma.sync.aligned.m16n8k16.row.col.f32.bf16.bf16.f32 "
        "{%0,%1,%2,%3}, {%4,%5,%6,%7}, {%8,%9}, {%0,%1,%2,%3};"
        : "+f"(d[0]), "+f"(d[1]), "+f"(d[2]), "+f"(d[3])
        : "r"(a.x), "r"(a.y), "r"(a.z), "r"(a.w), "r"(b0), "r"(b1));
}
__device__ __forceinline__ float sigmoid_fast(float x) { return 1.f / (1.f + __expf(-x)); }
__device__ __forceinline__ float tanh_fast(float x) { float e = __expf(2.f * x); return 1.f - 2.f / (e + 1.f); }

// orig gate col c = gate*512 + hcol -> pc = (hcol/8)*32 + gate*8 + hcol%8
__device__ __forceinline__ int cperm(int c) {
    int g = c >> 9, hc = c & 511;
    return ((hc >> 3) << 5) + (g << 3) + (hc & 7);
}

// ---------------- init ----------------
__global__ void init_kernel() {
    int i = blockIdx.x * blockDim.x + threadIdx.x;
    if (i == 0) { g_bar_arrive = 0; g_bar_epoch = 0; }
    if (i < 8 * 32 * 32) {
        g_hfh[0][i] = make_uint4(0, 0, 0, 0);
        g_hfl[0][i] = make_uint4(0, 0, 0, 0);
    }
}

// ---------------- U fragment prep ----------------
__global__ __launch_bounds__(256) void uf_prep(const float* __restrict__ U) {
    int i = blockIdx.x * 256 + threadIdx.x;      // 262144 total
    int l = i & 31, nt = (i >> 5) & 3, kt = (i >> 7) & 31, cta = i >> 12;
    int n = nt * 8 + (l >> 2);
    int k0 = kt * 16 + (l & 3) * 2;
    int c = (n >> 3) * 512 + cta * 8 + (n & 7);
    float u00 = U[(size_t)k0 * G4_ + c];
    float u01 = U[(size_t)(k0 + 1) * G4_ + c];
    float u10 = U[(size_t)(k0 + 8) * G4_ + c];
    float u11 = U[(size_t)(k0 + 9) * G4_ + c];
    uint32_t b0h, b0l, b1h, b1l;
    split2(u00, u01, b0h, b0l);
    split2(u10, u11, b1h, b1l);
    g_uf[i] = make_uint4(b0h, b1h, b0l, b1l);
}

// ---------------- phase 1: xW = x @ W + bias (fp32 SIMT, permuted store) -------
__global__ __launch_bounds__(256) void xw_gemm(const float* __restrict__ A,
                                               const float* __restrict__ Wm,
                                               const float* __restrict__ bias) {
    __shared__ float As[16][128];
    __shared__ float Bs[16][128];
    const int tid = threadIdx.x;
    const int rowA = blockIdx.y * 128;
    const int colB = blockIdx.x * 128;

    const int aRow = tid >> 2, aCol = (tid & 3) * 4;
    const int bRow = tid >> 5, bCol = (tid & 31) * 4;
    const int ty = tid >> 4, tx = tid & 15;

    float acc[8][8];
#pragma unroll
    for (int i = 0; i < 8; i++)
#pragma unroll
        for (int j = 0; j < 8; j++) acc[i][j] = 0.f;

    for (int k0 = 0; k0 < D_; k0 += 16) {
#pragma unroll
        for (int h = 0; h < 2; h++) {
            float4 v = *(const float4*)&A[(size_t)(rowA + aRow + h * 64) * D_ + k0 + aCol];
            As[aCol + 0][aRow + h * 64] = v.x;
            As[aCol + 1][aRow + h * 64] = v.y;
            As[aCol + 2][aRow + h * 64] = v.z;
            As[aCol + 3][aRow + h * 64] = v.w;
        }
#pragma unroll
        for (int h = 0; h < 2; h++) {
            float4 v = *(const float4*)&Wm[(size_t)(k0 + bRow + h * 8) * G4_ + colB + bCol];
            *(float4*)&Bs[bRow + h * 8][bCol] = v;
        }
        __syncthreads();
#pragma unroll
        for (int kk = 0; kk < 16; kk++) {
            float ra[8], rb[8];
            float4 a0 = *(const float4*)&As[kk][ty * 8];
            float4 a1 = *(const float4*)&As[kk][ty * 8 + 4];
            float4 b0 = *(const float4*)&Bs[kk][tx * 8];
            float4 b1 = *(const float4*)&Bs[kk][tx * 8 + 4];
            ra[0]=a0.x; ra[1]=a0.y; ra[2]=a0.z; ra[3]=a0.w;
            ra[4]=a1.x; ra[5]=a1.y; ra[6]=a1.z; ra[7]=a1.w;
            rb[0]=b0.x; rb[1]=b0.y; rb[2]=b0.z; rb[3]=b0.w;
            rb[4]=b1.x; rb[5]=b1.y; rb[6]=b1.z; rb[7]=b1.w;
#pragma unroll
            for (int i = 0; i < 8; i++)
#pragma unroll
                for (int j = 0; j < 8; j++)
                    acc[i][j] += ra[i] * rb[j];
        }
        __syncthreads();
    }

#pragma unroll
    for (int i = 0; i < 8; i++) {
        size_t r = (size_t)(rowA + ty * 8 + i);
#pragma unroll
        for (int j = 0; j < 8; j += 4) {
            int c = colB + tx * 8 + j;
            float4 v;
            v.x = acc[i][j + 0] + bias[c + 0];
            v.y = acc[i][j + 1] + bias[c + 1];
            v.z = acc[i][j + 2] + bias[c + 2];
            v.w = acc[i][j + 3] + bias[c + 3];
            *(float4*)&g_xw[r * G4_ + cperm(c)] = v;   // quad stays contiguous under perm
        }
    }
}

// ---------------- phase 2: persistent mma.sync recurrence ----------------------
// 64 CTAs, 8 warps. Warp w: K-chunk kt = 4w..4w+3 (K=64), full M=128, N=32.
// U frags persistent in registers; h A-frags streamed from gmem (fragment order).
// Partial K-sums reduced through padded smem; epilogue warp w: hcol-pair (w&3),
// row-half (w>>2); thread: rows r, r+8 x 2 hcols.
#define SPAD 34
#define SRED_ELEMS (8 * 128 * SPAD)

__global__ __launch_bounds__(RTHR, 1) void lstm_rec(float* __restrict__ out,
                                                    int write_hc) {
    extern __shared__ float sred[];
    const int tid = threadIdx.x;
    const int w = tid >> 5, l = tid & 31;
    const int cta = blockIdx.x;

    // ---- persistent U B-fragments ----
    uint4 Bf[4][4];
    {
        const uint4* ub = g_uf + (size_t)cta * 32 * 4 * 32;
#pragma unroll
        for (int i = 0; i < 4; i++)
#pragma unroll
            for (int nt = 0; nt < 4; nt++)
                Bf[i][nt] = __ldg(&ub[(((w * 4 + i) * 4) + nt) * 32 + l]);
    }

    // ---- epilogue role ----
    const int hp = w & 3, rh = w >> 2;
    const int r_lo = rh * 64 + (l & 7) + ((l >> 3) << 4);   // rows r_lo, r_lo+8
    const int kt_w = cta >> 1;                              // h-frag ktile this CTA writes
    const int regbase = (cta & 1) * 2;                      // a0/a1 vs a2/a3
    const int lane_frag = (l & 7) * 4 + hp;

    float creg[2][2] = {{0.f, 0.f}, {0.f, 0.f}};            // [rr][q]
    float hlast[2][2];

    for (int t = 0; t < T_; t++) {
        const int p = t & 1;
        const uint4* __restrict__ Ah = g_hfh[p];
        const uint4* __restrict__ Al = g_hfl[p];

        float acc[8][4][4];
#pragma unroll
        for (int mt = 0; mt < 8; mt++)
#pragma unroll
            for (int nt = 0; nt < 4; nt++)
#pragma unroll
                for (int q = 0; q < 4; q++) acc[mt][nt][q] = 0.f;

        // ---- mma mainloop: 8 mt x 4 kt x 4 nt x 3 products ----
#pragma unroll
        for (int i = 0; i < 4; i++) {
            const int kt = w * 4 + i;
#pragma unroll
            for (int mt = 0; mt < 8; mt++) {
                const int slot = (mt * 32 + kt) * 32 + l;
                uint4 ah = __ldcg(&Ah[slot]);
                uint4 al = __ldcg(&Al[slot]);
#pragma unroll
                for (int nt = 0; nt < 4; nt++) {
                    mma16816(acc[mt][nt], ah, Bf[i][nt].x, Bf[i][nt].y);  // hi*Uhi
                    mma16816(acc[mt][nt], ah, Bf[i][nt].z, Bf[i][nt].w);  // hi*Ulo
                    mma16816(acc[mt][nt], al, Bf[i][nt].x, Bf[i][nt].y);  // lo*Uhi
                }
            }
        }

        // ---- store partials to smem ----
        __syncthreads();
        {
            const int row0 = (l >> 2);
            const int n0 = 2 * (l & 3);
#pragma unroll
            for (int mt = 0; mt < 8; mt++)
#pragma unroll
                for (int nt = 0; nt < 4; nt++) {
                    int s = (w * 128 + mt * 16 + row0) * SPAD + nt * 8 + n0;
                    *(float2*)&sred[s]            = make_float2(acc[mt][nt][0], acc[mt][nt][1]);
                    *(float2*)&sred[s + 8 * SPAD] = make_float2(acc[mt][nt][2], acc[mt][nt][3]);
                }
        }
        __syncthreads();

        // ---- reduce + cell update (4 cells: rows {r_lo, r_lo+8} x hcols {2hp, 2hp+1}) ----
        float hnew[2][2];
#pragma unroll
        for (int rr = 0; rr < 2; rr++) {
            const int row = r_lo + rr * 8;
            float2 gsum[4];
#pragma unroll
            for (int g = 0; g < 4; g++) {
                float2 s = make_float2(0.f, 0.f);
#pragma unroll
                for (int pw = 0; pw < 8; pw++) {
                    float2 v = *(const float2*)&sred[(pw * 128 + row) * SPAD + g * 8 + 2 * hp];
                    s.x += v.x; s.y += v.y;
                }
                gsum[g] = s;
            }
            const float* xwb = g_xw + ((size_t)row * T_ + t) * G4_ + cta * 32;
#pragma unroll
            for (int g = 0; g < 4; g++) {
                float2 xv = __ldg((const float2*)&xwb[g * 8 + 2 * hp]);
                gsum[g].x += xv.x; gsum[g].y += xv.y;
            }
#pragma unroll
            for (int q = 0; q < 2; q++) {
                float gi = q ? gsum[0].y : gsum[0].x;
                float gf = q ? gsum[1].y : gsum[1].x;
                float gg = q ? gsum[2].y : gsum[2].x;
                float go = q ? gsum[3].y : gsum[3].x;
                float iv = sigmoid_fast(gi);
                float fv = sigmoid_fast(gf);
                float gv = tanh_fast(gg);
                float ov = sigmoid_fast(go);
                float c = fv * creg[rr][q] + iv * gv;
                creg[rr][q] = c;
                float h = ov * tanh_fast(c);
                hnew[rr][q] = h;
                hlast[rr][q] = h;
            }
            // hidden_sequence write: out[row][t][cta*8 + 2hp + {0,1}]
            *(float2*)&out[((size_t)row * T_ + t) * HS_ + cta * 8 + 2 * hp] =
                make_float2(hnew[rr][0], hnew[rr][1]);
        }

        // ---- h fragment write for next step ----
        {
            uint32_t hi0, lo0, hi1, lo1;
            split2(hnew[0][0], hnew[0][1], hi0, lo0);   // row r_lo     -> reg regbase
            split2(hnew[1][0], hnew[1][1], hi1, lo1);   // row r_lo + 8 -> reg regbase+1
            const int mtw = r_lo >> 4;
            const size_t byteoff = ((size_t)(mtw * 32 + kt_w) * 32 + lane_frag) * 16 + regbase * 4;
            *(uint2*)((char*)g_hfh[1 - p] + byteoff) = make_uint2(hi0, hi1);
            *(uint2*)((char*)g_hfl[1 - p] + byteoff) = make_uint2(lo0, lo1);
        }

        // ---- grid barrier ----
        if (t < T_ - 1) {
            __threadfence();
            __syncthreads();
            if (tid == 0) {
                unsigned int old = atomicAdd(&g_bar_arrive, 1);
                if (old == RCTA - 1) {
                    atomicExch(&g_bar_arrive, 0);
                    __threadfence();
                    g_bar_epoch = (unsigned)(t + 1);
                } else {
                    while (g_bar_epoch < (unsigned)(t + 1)) { }
                    __threadfence();
                }
            }
            __syncthreads();
        }
    }

    // ---- final (h_T, c_T) ----
    if (write_hc) {
        const size_t OH = (size_t)B_ * T_ * HS_;
#pragma unroll
        for (int rr = 0; rr < 2; rr++) {
            const int row = r_lo + rr * 8;
            *(float2*)&out[OH + (size_t)row * HS_ + cta * 8 + 2 * hp] =
                make_float2(hlast[rr][0], hlast[rr][1]);
            *(float2*)&out[OH + (size_t)B_ * HS_ + (size_t)row * HS_ + cta * 8 + 2 * hp] =
                make_float2(creg[rr][0], creg[rr][1]);
        }
    }
}

// ---------------- launch ----------------
extern "C" void kernel_launch(void* const* d_in, const int* in_sizes, int n_in,
                              void* d_out, int out_size) {
    const float* x    = (const float*)d_in[0];
    const float* Wm   = (const float*)d_in[1];
    const float* U    = (const float*)d_in[2];
    const float* bias = (const float*)d_in[3];
    float* out = (float*)d_out;
    (void)in_sizes; (void)n_in;

    const int smem_rec = SRED_ELEMS * (int)sizeof(float);   // 139264 B
    cudaFuncSetAttribute(lstm_rec, cudaFuncAttributeMaxDynamicSharedMemorySize, smem_rec);

    const long long need_hc = (long long)B_ * T_ * HS_ + 2LL * B_ * HS_;
    int write_hc = ((long long)out_size >= need_hc) ? 1 : 0;

    init_kernel<<<(8 * 32 * 32 + 255) / 256, 256>>>();
    uf_prep<<<(RCTA * 32 * 4 * 32) / 256, 256>>>(U);
    xw_gemm<<<dim3(G4_ / 128, M1_ / 128), 256>>>(x, Wm, bias);
    lstm_rec<<<RCTA, RTHR, smem_rec>>>(out, write_hc);
}

// round 5
// speedup vs baseline: 1.5719x; 1.0022x over previous
#include <cuda_runtime.h>
#include <cuda_bf16.h>
#include <cstdint>

#define B_   128
#define T_   1024
#define D_   256
#define HS_  512
#define G4_  2048
#define M1_  (B_ * T_)

#define RCTA 64
#define RTHR 256

// ---------------- device scratch ----------------
__device__ float g_xw[(size_t)M1_ * G4_];            // [(row*T+t)*2048 + pc]
__device__ uint4 g_uf[RCTA * 32 * 4 * 32];           // U frags [cta][kt][nt][lane]={b0h,b1h,b0l,b1l}
__device__ uint4 g_xfh[(size_t)8192 * 16 * 32];      // x A-frags hi [(rg*16+kt)*32+lane]
__device__ uint4 g_xfl[(size_t)8192 * 16 * 32];      // x A-frags lo
__device__ uint4 g_wf[16 * 16 * 16 * 32];            // W B-frags [cb][kt][ncol][lane]
__device__ uint4 g_hfh[2][8 * 32 * 32];              // h hi A-frags
__device__ uint4 g_hfl[2][8 * 32 * 32];              // h lo A-frags
__device__ unsigned int g_bar_arrive;
__device__ volatile unsigned int g_bar_epoch;

// ---------------- helpers ----------------
__device__ __forceinline__ uint32_t packbf(__nv_bfloat16 a, __nv_bfloat16 b) {
    return ((uint32_t)(*(uint16_t*)&b) << 16) | (uint32_t)(*(uint16_t*)&a);
}
__device__ __forceinline__ void split2(float a, float b, uint32_t& hi, uint32_t& lo) {
    __nv_bfloat16 ah = __float2bfloat16(a), bh = __float2bfloat16(b);
    __nv_bfloat16 al = __float2bfloat16(a - __bfloat162float(ah));
    __nv_bfloat16 bl = __float2bfloat16(b - __bfloat162float(bh));
    hi = packbf(ah, bh);
    lo = packbf(al, bl);
}
__device__ __forceinline__ void mma16816(float* d, const uint4& a, uint32_t b0, uint32_t b1) {
    asm volatile(
        "mma.sync.aligned.m16n8k16.row.col.f32.bf16.bf16.f32 "
        "{%0,%1,%2,%3}, {%4,%5,%6,%7}, {%8,%9}, {%0,%1,%2,%3};"
        : "+f"(d[0]), "+f"(d[1]), "+f"(d[2]), "+f"(d[3])
        : "r"(a.x), "r"(a.y), "r"(a.z), "r"(a.w), "r"(b0), "r"(b1));
}
__device__ __forceinline__ float sigmoid_fast(float x) { return 1.f / (1.f + __expf(-x)); }
__device__ __forceinline__ float tanh_fast(float x) { float e = __expf(2.f * x); return 1.f - 2.f / (e + 1.f); }

// orig gate col c = gate*512 + hcol -> pc = (hcol/8)*32 + gate*8 + hcol%8
__device__ __forceinline__ int cperm(int c) {
    int g = c >> 9, hc = c & 511;
    return ((hc >> 3) << 5) + (g << 3) + (hc & 7);
}

// ---------------- init ----------------
__global__ void init_kernel() {
    int i = blockIdx.x * blockDim.x + threadIdx.x;
    if (i == 0) { g_bar_arrive = 0; g_bar_epoch = 0; }
    if (i < 8 * 32 * 32) {
        g_hfh[0][i] = make_uint4(0, 0, 0, 0);
        g_hfl[0][i] = make_uint4(0, 0, 0, 0);
    }
}

// ---------------- U fragment prep ----------------
__global__ __launch_bounds__(256) void uf_prep(const float* __restrict__ U) {
    int i = blockIdx.x * 256 + threadIdx.x;
    int l = i & 31, nt = (i >> 5) & 3, kt = (i >> 7) & 31, cta = i >> 12;
    int n = nt * 8 + (l >> 2);
    int k0 = kt * 16 + (l & 3) * 2;
    int c = (n >> 3) * 512 + cta * 8 + (n & 7);
    float u00 = U[(size_t)k0 * G4_ + c];
    float u01 = U[(size_t)(k0 + 1) * G4_ + c];
    float u10 = U[(size_t)(k0 + 8) * G4_ + c];
    float u11 = U[(size_t)(k0 + 9) * G4_ + c];
    uint32_t b0h, b0l, b1h, b1l;
    split2(u00, u01, b0h, b0l);
    split2(u10, u11, b1h, b1l);
    g_uf[i] = make_uint4(b0h, b1h, b0l, b1l);
}

// ---------------- x fragment prep (A-frags for phase-1 GEMM) ----------------
__global__ __launch_bounds__(256) void split_xf(const float* __restrict__ x) {
    size_t i = (size_t)blockIdx.x * 256 + threadIdx.x;    // 4,194,304 total
    int l = (int)(i & 31), kt = (int)((i >> 5) & 15);
    int rg = (int)(i >> 9);
    int row = rg * 16 + (l >> 2);
    int k0 = kt * 16 + (l & 3) * 2;
    uint32_t hi[4], lo[4];
#pragma unroll
    for (int kh = 0; kh < 2; kh++)
#pragma unroll
        for (int rh = 0; rh < 2; rh++) {
            float2 v = *(const float2*)&x[(size_t)(row + 8 * rh) * D_ + k0 + 8 * kh];
            split2(v.x, v.y, hi[kh * 2 + rh], lo[kh * 2 + rh]);
        }
    g_xfh[i] = make_uint4(hi[0], hi[1], hi[2], hi[3]);
    g_xfl[i] = make_uint4(lo[0], lo[1], lo[2], lo[3]);
}

// ---------------- W fragment prep (B-frags) ----------------
__global__ __launch_bounds__(256) void wf_prep(const float* __restrict__ Wm) {
    int i = blockIdx.x * 256 + threadIdx.x;               // 131072 total
    int l = i & 31, nc = (i >> 5) & 15, kt = (i >> 9) & 15, cb = i >> 13;
    int n = cb * 128 + nc * 8 + (l >> 2);
    int k0 = kt * 16 + (l & 3) * 2;
    float u00 = Wm[(size_t)k0 * G4_ + n];
    float u01 = Wm[(size_t)(k0 + 1) * G4_ + n];
    float u10 = Wm[(size_t)(k0 + 8) * G4_ + n];
    float u11 = Wm[(size_t)(k0 + 9) * G4_ + n];
    uint32_t b0h, b0l, b1h, b1l;
    split2(u00, u01, b0h, b0l);
    split2(u10, u11, b1h, b1l);
    g_wf[i] = make_uint4(b0h, b1h, b0l, b1l);
}

// ---------------- phase 1: xW = x @ W + bias  (mma.sync, permuted store) -------
// grid (16 colblk, 1024 rowblk), 256 thr. Warp: wr=w&3 (32 rows), wc=w>>2 (64 cols).
__global__ __launch_bounds__(256) void xw_mma(const float* __restrict__ bias) {
    const int tid = threadIdx.x;
    const int w = tid >> 5, l = tid & 31;
    const int cb = blockIdx.x, rb = blockIdx.y;
    const int wr = w & 3, wc = w >> 2;

    float acc[2][8][4];
#pragma unroll
    for (int mt = 0; mt < 2; mt++)
#pragma unroll
        for (int nt = 0; nt < 8; nt++)
#pragma unroll
            for (int q = 0; q < 4; q++) acc[mt][nt][q] = 0.f;

#pragma unroll 4
    for (int kt = 0; kt < 16; kt++) {
        uint4 bf[8];
#pragma unroll
        for (int nt = 0; nt < 8; nt++)
            bf[nt] = __ldg(&g_wf[(((cb * 16 + kt) * 16) + wc * 8 + nt) * 32 + l]);
#pragma unroll
        for (int mt = 0; mt < 2; mt++) {
            size_t rg = (size_t)rb * 8 + wr * 2 + mt;
            uint4 ah = __ldg(&g_xfh[(rg * 16 + kt) * 32 + l]);
            uint4 al = __ldg(&g_xfl[(rg * 16 + kt) * 32 + l]);
#pragma unroll
            for (int nt = 0; nt < 8; nt++) {
                mma16816(acc[mt][nt], ah, bf[nt].x, bf[nt].y);
                mma16816(acc[mt][nt], ah, bf[nt].z, bf[nt].w);
                mma16816(acc[mt][nt], al, bf[nt].x, bf[nt].y);
            }
        }
    }

#pragma unroll
    for (int mt = 0; mt < 2; mt++) {
        int r0 = rb * 128 + wr * 32 + mt * 16 + (l >> 2);
#pragma unroll
        for (int nt = 0; nt < 8; nt++) {
            int c = cb * 128 + wc * 64 + nt * 8 + (l & 3) * 2;
            int pc = cperm(c);
            float2 bv = __ldg((const float2*)&bias[c]);
            *(float2*)&g_xw[(size_t)r0 * G4_ + pc] =
                make_float2(acc[mt][nt][0] + bv.x, acc[mt][nt][1] + bv.y);
            *(float2*)&g_xw[(size_t)(r0 + 8) * G4_ + pc] =
                make_float2(acc[mt][nt][2] + bv.x, acc[mt][nt][3] + bv.y);
        }
    }
}

// ---------------- phase 2: persistent mma.sync recurrence ----------------------
// 64 CTAs, 8 warps. Warp (mh=w>>2, kq=w&3): M=64 (4 mt), K=128 (kt=kq*8..+7), N=32.
// U frags via L1 (__ldg); h A-frags streamed via __ldcg with double-buffer prefetch.
#define SPAD 34
#define SRED_ELEMS (4 * 128 * SPAD)

__global__ __launch_bounds__(RTHR, 1) void lstm_rec(float* __restrict__ out,
                                                    int write_hc) {
    extern __shared__ float sred[];
    const int tid = threadIdx.x;
    const int w = tid >> 5, l = tid & 31;
    const int cta = blockIdx.x;
    const int mh = w >> 2, kq = w & 3;

    // epilogue role (4 cells: rows {r_lo, r_lo+8} x hcols {2hp, 2hp+1})
    const int hp = w & 3, rh = w >> 2;
    const int r_lo = rh * 64 + (l & 7) + ((l >> 3) << 4);
    const int kt_w = cta >> 1;
    const int regbase = (cta & 1) * 2;
    const int lane_frag = (l & 7) * 4 + hp;

    const uint4* __restrict__ ub = g_uf + (size_t)cta * 4096;

    float creg[2][2] = {{0.f, 0.f}, {0.f, 0.f}};
    float hlast[2][2];

    for (int t = 0; t < T_; t++) {
        const int p = t & 1;
        const uint4* __restrict__ Ah = g_hfh[p];
        const uint4* __restrict__ Al = g_hfl[p];

        // prefetch xw gate biases for the epilogue (DRAM latency hidden by mainloop)
        float2 xwp[2][4];
#pragma unroll
        for (int rr = 0; rr < 2; rr++) {
            const float* xwb = g_xw + ((size_t)(r_lo + rr * 8) * T_ + t) * G4_ + cta * 32;
#pragma unroll
            for (int g = 0; g < 4; g++)
                xwp[rr][g] = __ldcg((const float2*)&xwb[g * 8 + 2 * hp]);
        }

        float acc[4][4][4];
#pragma unroll
        for (int mt = 0; mt < 4; mt++)
#pragma unroll
            for (int nt = 0; nt < 4; nt++)
#pragma unroll
                for (int q = 0; q < 4; q++) acc[mt][nt][q] = 0.f;

        // ---- mainloop: kt = kq*8 + i, i = 0..7, double-buffered A prefetch ----
        uint4 ahb[2][4], alb[2][4];
        {
            const int kt = kq * 8;
#pragma unroll
            for (int mt = 0; mt < 4; mt++) {
                const int slot = (((mh * 4 + mt) * 32) + kt) * 32 + l;
                ahb[0][mt] = __ldcg(&Ah[slot]);
                alb[0][mt] = __ldcg(&Al[slot]);
            }
        }
#pragma unroll
        for (int i = 0; i < 8; i++) {
            const int cur = i & 1;
            if (i < 7) {
                const int ktn = kq * 8 + i + 1;
#pragma unroll
                for (int mt = 0; mt < 4; mt++) {
                    const int slot = (((mh * 4 + mt) * 32) + ktn) * 32 + l;
                    ahb[cur ^ 1][mt] = __ldcg(&Ah[slot]);
                    alb[cur ^ 1][mt] = __ldcg(&Al[slot]);
                }
            }
            const int kt = kq * 8 + i;
            uint4 bf[4];
#pragma unroll
            for (int nt = 0; nt < 4; nt++)
                bf[nt] = __ldg(&ub[(kt * 4 + nt) * 32 + l]);
#pragma unroll
            for (int mt = 0; mt < 4; mt++)
#pragma unroll
                for (int nt = 0; nt < 4; nt++) {
                    mma16816(acc[mt][nt], ahb[cur][mt], bf[nt].x, bf[nt].y);
                    mma16816(acc[mt][nt], ahb[cur][mt], bf[nt].z, bf[nt].w);
                    mma16816(acc[mt][nt], alb[cur][mt], bf[nt].x, bf[nt].y);
                }
        }

        // ---- store partials: slab kq, rows mh*64..+63 ----
        {
            const int row0 = (l >> 2), n0 = 2 * (l & 3);
#pragma unroll
            for (int mt = 0; mt < 4; mt++)
#pragma unroll
                for (int nt = 0; nt < 4; nt++) {
                    int s = (kq * 128 + mh * 64 + mt * 16 + row0) * SPAD + nt * 8 + n0;
                    *(float2*)&sred[s]            = make_float2(acc[mt][nt][0], acc[mt][nt][1]);
                    *(float2*)&sred[s + 8 * SPAD] = make_float2(acc[mt][nt][2], acc[mt][nt][3]);
                }
        }
        __syncthreads();

        // ---- reduce + cell update ----
        float hnew[2][2];
#pragma unroll
        for (int rr = 0; rr < 2; rr++) {
            const int row = r_lo + rr * 8;
            float2 gsum[4];
#pragma unroll
            for (int g = 0; g < 4; g++) {
                float2 s = xwp[rr][g];
#pragma unroll
                for (int q2 = 0; q2 < 4; q2++) {
                    float2 v = *(const float2*)&sred[(q2 * 128 + row) * SPAD + g * 8 + 2 * hp];
                    s.x += v.x; s.y += v.y;
                }
                gsum[g] = s;
            }
#pragma unroll
            for (int q = 0; q < 2; q++) {
                float gi = q ? gsum[0].y : gsum[0].x;
                float gf = q ? gsum[1].y : gsum[1].x;
                float gg = q ? gsum[2].y : gsum[2].x;
                float go = q ? gsum[3].y : gsum[3].x;
                float iv = sigmoid_fast(gi);
                float fv = sigmoid_fast(gf);
                float gv = tanh_fast(gg);
                float ov = sigmoid_fast(go);
                float c = fv * creg[rr][q] + iv * gv;
                creg[rr][q] = c;
                float h = ov * tanh_fast(c);
                hnew[rr][q] = h;
                hlast[rr][q] = h;
            }
            *(float2*)&out[((size_t)row * T_ + t) * HS_ + cta * 8 + 2 * hp] =
                make_float2(hnew[rr][0], hnew[rr][1]);
        }

        // ---- h fragment write for next step ----
        {
            uint32_t hi0, lo0, hi1, lo1;
            split2(hnew[0][0], hnew[0][1], hi0, lo0);
            split2(hnew[1][0], hnew[1][1], hi1, lo1);
            const int mtw = r_lo >> 4;
            const size_t byteoff = ((size_t)(mtw * 32 + kt_w) * 32 + lane_frag) * 16 + regbase * 4;
            *(uint2*)((char*)g_hfh[1 - p] + byteoff) = make_uint2(hi0, hi1);
            *(uint2*)((char*)g_hfl[1 - p] + byteoff) = make_uint2(lo0, lo1);
        }

        // ---- grid barrier ----
        if (t < T_ - 1) {
            __threadfence();
            __syncthreads();
            if (tid == 0) {
                unsigned int old = atomicAdd(&g_bar_arrive, 1);
                if (old == RCTA - 1) {
                    atomicExch(&g_bar_arrive, 0);
                    __threadfence();
                    g_bar_epoch = (unsigned)(t + 1);
                } else {
                    while (g_bar_epoch < (unsigned)(t + 1)) { }
                    __threadfence();
                }
            }
            __syncthreads();
        }
    }

    if (write_hc) {
        const size_t OH = (size_t)B_ * T_ * HS_;
#pragma unroll
        for (int rr = 0; rr < 2; rr++) {
            const int row = r_lo + rr * 8;
            *(float2*)&out[OH + (size_t)row * HS_ + cta * 8 + 2 * hp] =
                make_float2(hlast[rr][0], hlast[rr][1]);
            *(float2*)&out[OH + (size_t)B_ * HS_ + (size_t)row * HS_ + cta * 8 + 2 * hp] =
                make_float2(creg[rr][0], creg[rr][1]);
        }
    }
}

// ---------------- launch ----------------
extern "C" void kernel_launch(void* const* d_in, const int* in_sizes, int n_in,
                              void* d_out, int out_size) {
    const float* x    = (const float*)d_in[0];
    const float* Wm   = (const float*)d_in[1];
    const float* U    = (const float*)d_in[2];
    const float* bias = (const float*)d_in[3];
    float* out = (float*)d_out;
    (void)in_sizes; (void)n_in;

    const int smem_rec = SRED_ELEMS * (int)sizeof(float);   // 69632 B
    cudaFuncSetAttribute(lstm_rec, cudaFuncAttributeMaxDynamicSharedMemorySize, smem_rec);

    const long long need_hc = (long long)B_ * T_ * HS_ + 2LL * B_ * HS_;
    int write_hc = ((long long)out_size >= need_hc) ? 1 : 0;

    init_kernel<<<32, 256>>>();
    split_xf<<<16384, 256>>>(x);
    wf_prep<<<512, 256>>>(Wm);
    uf_prep<<<1024, 256>>>(U);
    xw_mma<<<dim3(16, 1024), 256>>>(bias);
    lstm_rec<<<RCTA, RTHR, smem_rec>>>(out, write_hc);
}

// round 8
// speedup vs baseline: 2.0417x; 1.2988x over previous
#include <cuda_runtime.h>
#include <cuda_bf16.h>
#include <cstdint>

#define B_   128
#define T_   1024
#define D_   256
#define HS_  512
#define G4_  2048
#define M1_  (B_ * T_)

#define RCTA 64
#define RTHR 512

// ---------------- device scratch ----------------
__device__ float g_xw[(size_t)M1_ * G4_];            // [(row*T+t)*2048 + pc], row-major
__device__ uint4 g_uf[RCTA * 32 * 4 * 32];           // U frags [cta][kt][nt][lane]
__device__ uint4 g_xfh[(size_t)8192 * 16 * 32];      // x A-frags hi
__device__ uint4 g_xfl[(size_t)8192 * 16 * 32];      // x A-frags lo
__device__ uint4 g_wf[16 * 16 * 16 * 32];            // W B-frags
__device__ uint4 g_hfh[2][8 * 32 * 32];              // h hi A-frags
__device__ uint4 g_hfl[2][8 * 32 * 32];              // h lo A-frags
__device__ unsigned int g_bar_arrive;
__device__ volatile unsigned int g_bar_epoch;

// ---------------- helpers ----------------
__device__ __forceinline__ uint32_t packbf(__nv_bfloat16 a, __nv_bfloat16 b) {
    return ((uint32_t)(*(uint16_t*)&b) << 16) | (uint32_t)(*(uint16_t*)&a);
}
__device__ __forceinline__ void split2(float a, float b, uint32_t& hi, uint32_t& lo) {
    __nv_bfloat16 ah = __float2bfloat16(a), bh = __float2bfloat16(b);
    __nv_bfloat16 al = __float2bfloat16(a - __bfloat162float(ah));
    __nv_bfloat16 bl = __float2bfloat16(b - __bfloat162float(bh));
    hi = packbf(ah, bh);
    lo = packbf(al, bl);
}
__device__ __forceinline__ void mma16816(float* d, const uint4& a, uint32_t b0, uint32_t b1) {
    asm volatile(
        "mma.sync.aligned.m16n8k16.row.col.f32.bf16.bf16.f32 "
        "{%0,%1,%2,%3}, {%4,%5,%6,%7}, {%8,%9}, {%0,%1,%2,%3};"
        : "+f"(d[0]), "+f"(d[1]), "+f"(d[2]), "+f"(d[3])
        : "r"(a.x), "r"(a.y), "r"(a.z), "r"(a.w), "r"(b0), "r"(b1));
}
__device__ __forceinline__ float sigmoid_fast(float x) { return 1.f / (1.f + __expf(-x)); }
__device__ __forceinline__ float tanh_fast(float x) { float e = __expf(2.f * x); return 1.f - 2.f / (e + 1.f); }

// orig gate col c = gate*512 + hcol -> pc = (hcol/8)*32 + gate*8 + hcol%8
__device__ __forceinline__ int cperm(int c) {
    int g = c >> 9, hc = c & 511;
    return ((hc >> 3) << 5) + (g << 3) + (hc & 7);
}

// ---------------- init ----------------
__global__ void init_kernel() {
    int i = blockIdx.x * blockDim.x + threadIdx.x;
    if (i == 0) { g_bar_arrive = 0; g_bar_epoch = 0; }
    if (i < 8 * 32 * 32) {
        g_hfh[0][i] = make_uint4(0, 0, 0, 0);
        g_hfl[0][i] = make_uint4(0, 0, 0, 0);
    }
}

// ---------------- U fragment prep ----------------
__global__ __launch_bounds__(256) void uf_prep(const float* __restrict__ U) {
    int i = blockIdx.x * 256 + threadIdx.x;
    int l = i & 31, nt = (i >> 5) & 3, kt = (i >> 7) & 31, cta = i >> 12;
    int n = nt * 8 + (l >> 2);
    int k0 = kt * 16 + (l & 3) * 2;
    int c = (n >> 3) * 512 + cta * 8 + (n & 7);
    float u00 = U[(size_t)k0 * G4_ + c];
    float u01 = U[(size_t)(k0 + 1) * G4_ + c];
    float u10 = U[(size_t)(k0 + 8) * G4_ + c];
    float u11 = U[(size_t)(k0 + 9) * G4_ + c];
    uint32_t b0h, b0l, b1h, b1l;
    split2(u00, u01, b0h, b0l);
    split2(u10, u11, b1h, b1l);
    g_uf[i] = make_uint4(b0h, b1h, b0l, b1l);
}

// ---------------- x fragment prep ----------------
__global__ __launch_bounds__(256) void split_xf(const float* __restrict__ x) {
    size_t i = (size_t)blockIdx.x * 256 + threadIdx.x;
    int l = (int)(i & 31), kt = (int)((i >> 5) & 15);
    int rg = (int)(i >> 9);
    int row = rg * 16 + (l >> 2);
    int k0 = kt * 16 + (l & 3) * 2;
    uint32_t hi[4], lo[4];
#pragma unroll
    for (int kh = 0; kh < 2; kh++)
#pragma unroll
        for (int rh = 0; rh < 2; rh++) {
            float2 v = *(const float2*)&x[(size_t)(row + 8 * rh) * D_ + k0 + 8 * kh];
            split2(v.x, v.y, hi[kh * 2 + rh], lo[kh * 2 + rh]);
        }
    g_xfh[i] = make_uint4(hi[0], hi[1], hi[2], hi[3]);
    g_xfl[i] = make_uint4(lo[0], lo[1], lo[2], lo[3]);
}

// ---------------- W fragment prep ----------------
__global__ __launch_bounds__(256) void wf_prep(const float* __restrict__ Wm) {
    int i = blockIdx.x * 256 + threadIdx.x;
    int l = i & 31, nc = (i >> 5) & 15, kt = (i >> 9) & 15, cb = i >> 13;
    int n = cb * 128 + nc * 8 + (l >> 2);
    int k0 = kt * 16 + (l & 3) * 2;
    float u00 = Wm[(size_t)k0 * G4_ + n];
    float u01 = Wm[(size_t)(k0 + 1) * G4_ + n];
    float u10 = Wm[(size_t)(k0 + 8) * G4_ + n];
    float u11 = Wm[(size_t)(k0 + 9) * G4_ + n];
    uint32_t b0h, b0l, b1h, b1l;
    split2(u00, u01, b0h, b0l);
    split2(u10, u11, b1h, b1l);
    g_wf[i] = make_uint4(b0h, b1h, b0l, b1l);
}

// ---------------- phase 1: xW = x @ W + bias (mma.sync) ----------------
__global__ __launch_bounds__(256) void xw_mma(const float* __restrict__ bias) {
    const int tid = threadIdx.x;
    const int w = tid >> 5, l = tid & 31;
    const int cb = blockIdx.x, rb = blockIdx.y;
    const int wr = w & 3, wc = w >> 2;

    float acc[2][8][4];
#pragma unroll
    for (int mt = 0; mt < 2; mt++)
#pragma unroll
        for (int nt = 0; nt < 8; nt++)
#pragma unroll
            for (int q = 0; q < 4; q++) acc[mt][nt][q] = 0.f;

#pragma unroll 4
    for (int kt = 0; kt < 16; kt++) {
        uint4 bf[8];
#pragma unroll
        for (int nt = 0; nt < 8; nt++)
            bf[nt] = __ldg(&g_wf[(((cb * 16 + kt) * 16) + wc * 8 + nt) * 32 + l]);
#pragma unroll
        for (int mt = 0; mt < 2; mt++) {
            size_t rg = (size_t)rb * 8 + wr * 2 + mt;
            uint4 ah = __ldg(&g_xfh[(rg * 16 + kt) * 32 + l]);
            uint4 al = __ldg(&g_xfl[(rg * 16 + kt) * 32 + l]);
#pragma unroll
            for (int nt = 0; nt < 8; nt++) {
                mma16816(acc[mt][nt], ah, bf[nt].x, bf[nt].y);
                mma16816(acc[mt][nt], ah, bf[nt].z, bf[nt].w);
                mma16816(acc[mt][nt], al, bf[nt].x, bf[nt].y);
            }
        }
    }

#pragma unroll
    for (int mt = 0; mt < 2; mt++) {
        int r0 = rb * 128 + wr * 32 + mt * 16 + (l >> 2);
#pragma unroll
        for (int nt = 0; nt < 8; nt++) {
            int c = cb * 128 + wc * 64 + nt * 8 + (l & 3) * 2;
            int pc = cperm(c);
            float2 bv = __ldg((const float2*)&bias[c]);
            *(float2*)&g_xw[(size_t)r0 * G4_ + pc] =
                make_float2(acc[mt][nt][0] + bv.x, acc[mt][nt][1] + bv.y);
            *(float2*)&g_xw[(size_t)(r0 + 8) * G4_ + pc] =
                make_float2(acc[mt][nt][2] + bv.x, acc[mt][nt][3] + bv.y);
        }
    }
}

// ---------------- phase 2: persistent mma.sync recurrence ----------------
// 64 CTAs x 512 thr (16 warps). Warp (mq=w>>2, kq=w&3): M=32 (2 mt), K=64 (8 kt), N=32.
#define SPAD  34
#define XPAD  36
#define SRED_ELEMS (4 * 128 * SPAD)
#define SMEM_ELEMS (SRED_ELEMS + 128 * XPAD)

__global__ __launch_bounds__(RTHR, 1) void lstm_rec(float* __restrict__ out,
                                                    int write_hc) {
    extern __shared__ float smemf[];
    float* sred = smemf;
    float* xw_s = smemf + SRED_ELEMS;

    const int tid = threadIdx.x;
    const int w = tid >> 5, l = tid & 31;
    const int cta = blockIdx.x;
    const int mq = w >> 2, kq = w & 3;

    // epilogue role: 2 cells = row_e x hcols {2hp, 2hp+1}
    const int row_e = tid >> 2, hp = tid & 3;
    const int kt_w = cta >> 1;
    const int regb = (cta & 1) * 2 + ((row_e >> 3) & 1);
    const size_t fragidx = ((size_t)(row_e >> 4) * 32 + kt_w) * 32 + (row_e & 7) * 4 + hp;

    const uint4* __restrict__ ub = g_uf + (size_t)cta * 4096;

    float creg[2] = {0.f, 0.f};
    float hlast[2];

    for (int t = 0; t < T_; t++) {
        const int p = t & 1;
        const uint4* __restrict__ Ah = g_hfh[p];
        const uint4* __restrict__ Al = g_hfl[p];

        // coalesced xw stage loads (held in regs through mainloop)
        float4 xr[2];
#pragma unroll
        for (int j = 0; j < 2; j++) {
            int rw = w * 8 + j * 4 + (l >> 3);
            xr[j] = __ldcg((const float4*)&g_xw[((size_t)rw * T_ + t) * G4_ + cta * 32 + (l & 7) * 4]);
        }

        float acc[2][4][4];
#pragma unroll
        for (int mt = 0; mt < 2; mt++)
#pragma unroll
            for (int nt = 0; nt < 4; nt++)
#pragma unroll
                for (int q = 0; q < 4; q++) acc[mt][nt][q] = 0.f;

        // ---- mainloop: kt = kq*8 + i, double-buffered A ----
        uint4 bh[2][2], bl[2][2];
#pragma unroll
        for (int mt = 0; mt < 2; mt++) {
            const int slot = (((mq * 2 + mt) * 32) + kq * 8) * 32 + l;
            bh[0][mt] = __ldcg(&Ah[slot]);
            bl[0][mt] = __ldcg(&Al[slot]);
        }
#pragma unroll
        for (int i = 0; i < 8; i++) {
            const int cur = i & 1;
            if (i < 7) {
                const int ktn = kq * 8 + i + 1;
#pragma unroll
                for (int mt = 0; mt < 2; mt++) {
                    const int slot = (((mq * 2 + mt) * 32) + ktn) * 32 + l;
                    bh[cur ^ 1][mt] = __ldcg(&Ah[slot]);
                    bl[cur ^ 1][mt] = __ldcg(&Al[slot]);
                }
            }
            const int kt = kq * 8 + i;
            uint4 bf[4];
#pragma unroll
            for (int nt = 0; nt < 4; nt++)
                bf[nt] = __ldg(&ub[(kt * 4 + nt) * 32 + l]);
#pragma unroll
            for (int mt = 0; mt < 2; mt++)
#pragma unroll
                for (int nt = 0; nt < 4; nt++) {
                    mma16816(acc[mt][nt], bh[cur][mt], bf[nt].x, bf[nt].y);
                    mma16816(acc[mt][nt], bh[cur][mt], bf[nt].z, bf[nt].w);
                    mma16816(acc[mt][nt], bl[cur][mt], bf[nt].x, bf[nt].y);
                }
        }

        // ---- partials + xw to smem ----
        {
            const int row0 = (l >> 2), n0 = 2 * (l & 3);
#pragma unroll
            for (int mt = 0; mt < 2; mt++)
#pragma unroll
                for (int nt = 0; nt < 4; nt++) {
                    int s = (kq * 128 + (mq * 2 + mt) * 16 + row0) * SPAD + nt * 8 + n0;
                    *(float2*)&sred[s]            = make_float2(acc[mt][nt][0], acc[mt][nt][1]);
                    *(float2*)&sred[s + 8 * SPAD] = make_float2(acc[mt][nt][2], acc[mt][nt][3]);
                }
#pragma unroll
            for (int j = 0; j < 2; j++)
                *(float4*)&xw_s[(w * 8 + j * 4 + (l >> 3)) * XPAD + (l & 7) * 4] = xr[j];
        }
        __syncthreads();

        // ---- reduce + cell update ----
        float2 gsum[4];
#pragma unroll
        for (int g = 0; g < 4; g++) {
            float2 s = *(const float2*)&xw_s[row_e * XPAD + g * 8 + 2 * hp];
#pragma unroll
            for (int q2 = 0; q2 < 4; q2++) {
                float2 v = *(const float2*)&sred[(q2 * 128 + row_e) * SPAD + g * 8 + 2 * hp];
                s.x += v.x; s.y += v.y;
            }
            gsum[g] = s;
        }
        float hnew[2];
#pragma unroll
        for (int q = 0; q < 2; q++) {
            float gi = q ? gsum[0].y : gsum[0].x;
            float gf = q ? gsum[1].y : gsum[1].x;
            float gg = q ? gsum[2].y : gsum[2].x;
            float go = q ? gsum[3].y : gsum[3].x;
            float iv = sigmoid_fast(gi);
            float fv = sigmoid_fast(gf);
            float gv = tanh_fast(gg);
            float ov = sigmoid_fast(go);
            float c = fv * creg[q] + iv * gv;
            creg[q] = c;
            float h = ov * tanh_fast(c);
            hnew[q] = h;
            hlast[q] = h;
        }
        *(float2*)&out[((size_t)row_e * T_ + t) * HS_ + cta * 8 + 2 * hp] =
            make_float2(hnew[0], hnew[1]);

        // h fragment write for next step
        {
            uint32_t hi, lo;
            split2(hnew[0], hnew[1], hi, lo);
            *(uint32_t*)((char*)g_hfh[1 - p] + fragidx * 16 + regb * 4) = hi;
            *(uint32_t*)((char*)g_hfl[1 - p] + fragidx * 16 + regb * 4) = lo;
        }

        // ---- grid barrier (proven R4/R5 atomic arrive + epoch spin) ----
        if (t < T_ - 1) {
            __threadfence();
            __syncthreads();
            if (tid == 0) {
                unsigned int old = atomicAdd(&g_bar_arrive, 1);
                if (old == RCTA - 1) {
                    atomicExch(&g_bar_arrive, 0);
                    __threadfence();
                    g_bar_epoch = (unsigned)(t + 1);
                } else {
                    while (g_bar_epoch < (unsigned)(t + 1)) { }
                    __threadfence();
                }
            }
            __syncthreads();
        }
    }

    if (write_hc) {
        const size_t OH = (size_t)B_ * T_ * HS_;
        *(float2*)&out[OH + (size_t)row_e * HS_ + cta * 8 + 2 * hp] =
            make_float2(hlast[0], hlast[1]);
        *(float2*)&out[OH + (size_t)B_ * HS_ + (size_t)row_e * HS_ + cta * 8 + 2 * hp] =
            make_float2(creg[0], creg[1]);
    }
}

// ---------------- launch ----------------
extern "C" void kernel_launch(void* const* d_in, const int* in_sizes, int n_in,
                              void* d_out, int out_size) {
    const float* x    = (const float*)d_in[0];
    const float* Wm   = (const float*)d_in[1];
    const float* U    = (const float*)d_in[2];
    const float* bias = (const float*)d_in[3];
    float* out = (float*)d_out;
    (void)in_sizes; (void)n_in;

    const int smem_rec = SMEM_ELEMS * (int)sizeof(float);   // 88064 B
    cudaFuncSetAttribute(lstm_rec, cudaFuncAttributeMaxDynamicSharedMemorySize, smem_rec);

    const long long need_hc = (long long)B_ * T_ * HS_ + 2LL * B_ * HS_;
    int write_hc = ((long long)out_size >= need_hc) ? 1 : 0;

    init_kernel<<<32, 256>>>();
    split_xf<<<16384, 256>>>(x);
    wf_prep<<<512, 256>>>(Wm);
    uf_prep<<<1024, 256>>>(U);
    xw_mma<<<dim3(16, 1024), 256>>>(bias);
    lstm_rec<<<RCTA, RTHR, smem_rec>>>(out, write_hc);
}